// round 1
// baseline (speedup 1.0000x reference)
#include <cuda_runtime.h>
#include <math.h>

// ---------------------------------------------------------------------------
// Problem constants
// ---------------------------------------------------------------------------
#define NV   16384      // nodes
#define DV   128        // node dim
#define EDV  32         // edge feat dim
#define EV   262144     // edges
#define GV   32         // graphs
#define SV   512        // seq per graph
#define HV   4          // heads
#define HDV  32         // head dim

// ---------------------------------------------------------------------------
// Scratch buffers (device globals; no allocation allowed)
// ---------------------------------------------------------------------------
__device__ float g_xn   [NV * DV];
__device__ float g_aggr [NV * DV];
__device__ float g_t1   [NV * DV];
__device__ float g_hloc [NV * DV];
__device__ float g_qkv  [NV * 3 * DV];
__device__ float g_obuf [NV * DV];
__device__ float g_hattn[NV * DV];
__device__ float g_h1   [NV * DV];
__device__ float g_ffn  [NV * 2 * DV];
__device__ float g_ffu  [NV * DV];

__device__ __forceinline__ float gelu_f(float v) {
    return 0.5f * v * (1.0f + erff(v * 0.70710678118654752f));
}

// ---------------------------------------------------------------------------
// LayerNorm over D=128 with up to 3 summed inputs. One warp per row.
// block = 256 threads (8 rows), grid = N/8
// ---------------------------------------------------------------------------
__global__ __launch_bounds__(256) void ln_kernel(
    const float* __restrict__ a, const float* __restrict__ b,
    const float* __restrict__ c, const float* __restrict__ g,
    const float* __restrict__ be, float* __restrict__ out)
{
    int row  = blockIdx.x * 8 + (threadIdx.x >> 5);
    int lane = threadIdx.x & 31;
    size_t off = (size_t)row * 128 + lane * 4;
    float4 v = *(const float4*)(a + off);
    if (b) {
        float4 u = *(const float4*)(b + off);
        v.x += u.x; v.y += u.y; v.z += u.z; v.w += u.w;
    }
    if (c) {
        float4 u = *(const float4*)(c + off);
        v.x += u.x; v.y += u.y; v.z += u.z; v.w += u.w;
    }
    float s  = v.x + v.y + v.z + v.w;
    float ss = v.x*v.x + v.y*v.y + v.z*v.z + v.w*v.w;
    #pragma unroll
    for (int o = 16; o > 0; o >>= 1) {
        s  += __shfl_xor_sync(0xffffffffu, s,  o);
        ss += __shfl_xor_sync(0xffffffffu, ss, o);
    }
    float mean = s * (1.0f / 128.0f);
    float var  = ss * (1.0f / 128.0f) - mean * mean;
    float rstd = rsqrtf(var + 1e-5f);
    float4 gg = *(const float4*)(g  + lane * 4);
    float4 bb = *(const float4*)(be + lane * 4);
    float4 o4;
    o4.x = (v.x - mean) * rstd * gg.x + bb.x;
    o4.y = (v.y - mean) * rstd * gg.y + bb.y;
    o4.z = (v.z - mean) * rstd * gg.z + bb.z;
    o4.w = (v.w - mean) * rstd * gg.w + bb.w;
    *(float4*)(out + off) = o4;
}

// ---------------------------------------------------------------------------
// Generic fp32 GEMM: C[M,NN] = act( [A1|A2][M,K1+K2] @ B[K,NN] + bias )
// BM=128, BN=64, BK=16, 256 threads, 8x4 register tiles.
// ---------------------------------------------------------------------------
template<bool GELU>
__global__ __launch_bounds__(256) void gemm_bias_kernel(
    const float* __restrict__ A1, int K1,
    const float* __restrict__ A2, int K2,
    const float* __restrict__ B,
    const float* __restrict__ bias,
    float* __restrict__ C, int M, int NN)
{
    const int K = K1 + K2;
    const int T = K >> 4;
    __shared__ float As[2][16 * 128];
    __shared__ float Bs[2][16 * 64];
    const int t  = threadIdx.x;
    const int m0 = blockIdx.x * 128;
    const int n0 = blockIdx.y * 64;
    const int mg = t >> 4;       // 0..15 (lanes 0..15 share mg -> broadcast a)
    const int ng = t & 15;       // 0..15

    float4 ra[2], rb;
    auto ldg_tile = [&](int kt) {
        int kb = kt * 16;
        #pragma unroll
        for (int i = 0; i < 2; i++) {
            int cc = t + i * 256;
            int m = cc >> 2, k4 = cc & 3;
            int gk = kb + k4 * 4;
            const float* src = (gk < K1)
                ? (A1 + (size_t)(m0 + m) * K1 + gk)
                : (A2 + (size_t)(m0 + m) * K2 + (gk - K1));
            ra[i] = *(const float4*)src;
        }
        int r = t >> 4, c4 = t & 15;
        rb = *(const float4*)(B + (size_t)(kb + r) * NN + n0 + c4 * 4);
    };
    auto sts_tile = [&](int buf) {
        #pragma unroll
        for (int i = 0; i < 2; i++) {
            int cc = t + i * 256;
            int m = cc >> 2, k4 = cc & 3;
            As[buf][(k4 * 4 + 0) * 128 + m] = ra[i].x;
            As[buf][(k4 * 4 + 1) * 128 + m] = ra[i].y;
            As[buf][(k4 * 4 + 2) * 128 + m] = ra[i].z;
            As[buf][(k4 * 4 + 3) * 128 + m] = ra[i].w;
        }
        int r = t >> 4, c4 = t & 15;
        *(float4*)&Bs[buf][r * 64 + c4 * 4] = rb;
    };

    float acc[8][4];
    #pragma unroll
    for (int i = 0; i < 8; i++)
        #pragma unroll
        for (int j = 0; j < 4; j++) acc[i][j] = 0.0f;

    ldg_tile(0); sts_tile(0);
    for (int kt = 0; kt < T; kt++) {
        __syncthreads();
        if (kt + 1 < T) ldg_tile(kt + 1);
        const float* ap = As[kt & 1];
        const float* bp = Bs[kt & 1];
        #pragma unroll
        for (int k = 0; k < 16; k++) {
            float4 a0 = *(const float4*)(ap + k * 128 + mg * 8);
            float4 a1 = *(const float4*)(ap + k * 128 + mg * 8 + 4);
            float4 b0 = *(const float4*)(bp + k * 64 + ng * 4);
            float a[8] = {a0.x, a0.y, a0.z, a0.w, a1.x, a1.y, a1.z, a1.w};
            float bv[4] = {b0.x, b0.y, b0.z, b0.w};
            #pragma unroll
            for (int i = 0; i < 8; i++)
                #pragma unroll
                for (int j = 0; j < 4; j++)
                    acc[i][j] = fmaf(a[i], bv[j], acc[i][j]);
        }
        if (kt + 1 < T) sts_tile((kt + 1) & 1);
    }

    float4 bv4 = *(const float4*)(bias + n0 + ng * 4);
    #pragma unroll
    for (int i = 0; i < 8; i++) {
        float4 o4;
        o4.x = acc[i][0] + bv4.x;
        o4.y = acc[i][1] + bv4.y;
        o4.z = acc[i][2] + bv4.z;
        o4.w = acc[i][3] + bv4.w;
        if (GELU) {
            o4.x = gelu_f(o4.x); o4.y = gelu_f(o4.y);
            o4.z = gelu_f(o4.z); o4.w = gelu_f(o4.w);
        }
        *(float4*)(C + (size_t)(m0 + mg * 8 + i) * NN + n0 + ng * 4) = o4;
    }
}

// ---------------------------------------------------------------------------
// Fused edge-message MLP + scatter-add.
// Block: 64 edges, 256 threads.
//   A = [xn[dst] | xn[src] | edge_attr]  [64 x 288]  (gathered to SMEM)
//   H1 = gelu(A @ W1 + b1)               [64 x 256]  (SMEM)
//   msg = H1 @ W2 + b2                   [64 x 128]
//   atomicAdd into aggr[dst]
// SMEM: As 288*64 + H1 256*68 + Bs 2*16*256 = 44032 floats = 176128 B
// ---------------------------------------------------------------------------
__global__ __launch_bounds__(256) void edge_kernel(
    const float* __restrict__ xn,
    const int*   __restrict__ eidx,     // [2][E]: row0=src, row1=dst
    const float* __restrict__ ea,
    const float* __restrict__ W1, const float* __restrict__ b1,
    const float* __restrict__ W2, const float* __restrict__ b2,
    float* __restrict__ aggr)
{
    extern __shared__ float sm[];
    float* As = sm;                    // [288][64]
    float* H1 = sm + 288 * 64;         // [256][68]
    float* Bs = H1 + 256 * 68;         // [2][16*256]
    const int t  = threadIdx.x;
    const int e0 = blockIdx.x * 64;
    const int* srcp = eidx;
    const int* dstp = eidx + EV;

    // ---- gather A tile (k-major, stride 64) ----
    #pragma unroll
    for (int it = 0; it < 18; it++) {
        int cc = t + it * 256;          // 0..4607
        int e  = cc & 63;
        int k4 = cc >> 6;               // 0..71
        int ge = e0 + e;
        float4 v;
        if (k4 < 32)       v = *(const float4*)(xn + (size_t)dstp[ge] * 128 + k4 * 4);
        else if (k4 < 64)  v = *(const float4*)(xn + (size_t)srcp[ge] * 128 + (k4 - 32) * 4);
        else               v = *(const float4*)(ea + (size_t)ge * 32 + (k4 - 64) * 4);
        int kb = k4 * 4;
        As[(kb + 0) * 64 + e] = v.x;
        As[(kb + 1) * 64 + e] = v.y;
        As[(kb + 2) * 64 + e] = v.z;
        As[(kb + 3) * 64 + e] = v.w;
    }

    const int mg = t >> 5;   // 0..7  (full-warp broadcast for a)
    const int ng = t & 31;   // 0..31

    // ---- GEMM1: [64,288] @ [288,256] ----
    float4 st1[4];
    auto ldg1 = [&](int kt) {
        #pragma unroll
        for (int i = 0; i < 4; i++) {
            int f = t + i * 256;
            int r = f >> 6, c4 = f & 63;
            st1[i] = *(const float4*)(W1 + (size_t)(kt * 16 + r) * 256 + c4 * 4);
        }
    };
    auto sts1 = [&](int buf) {
        #pragma unroll
        for (int i = 0; i < 4; i++) {
            int f = t + i * 256;
            int r = f >> 6, c4 = f & 63;
            *(float4*)&Bs[buf * 4096 + r * 256 + c4 * 4] = st1[i];
        }
    };

    float acc[8][8];
    #pragma unroll
    for (int i = 0; i < 8; i++)
        #pragma unroll
        for (int j = 0; j < 8; j++) acc[i][j] = 0.0f;

    ldg1(0); sts1(0);
    for (int kt = 0; kt < 18; kt++) {
        __syncthreads();                 // also orders gather at kt==0
        if (kt < 17) ldg1(kt + 1);
        const float* bp = Bs + (kt & 1) * 4096;
        #pragma unroll
        for (int k = 0; k < 16; k++) {
            const float* ar = As + (kt * 16 + k) * 64 + mg * 8;
            float4 a0 = *(const float4*)ar;
            float4 a1 = *(const float4*)(ar + 4);
            float4 b0 = *(const float4*)(bp + k * 256 + ng * 8);
            float4 b1 = *(const float4*)(bp + k * 256 + ng * 8 + 4);
            float a[8] = {a0.x, a0.y, a0.z, a0.w, a1.x, a1.y, a1.z, a1.w};
            float bv[8] = {b0.x, b0.y, b0.z, b0.w, b1.x, b1.y, b1.z, b1.w};
            #pragma unroll
            for (int i = 0; i < 8; i++)
                #pragma unroll
                for (int j = 0; j < 8; j++)
                    acc[i][j] = fmaf(a[i], bv[j], acc[i][j]);
        }
        if (kt < 17) sts1((kt + 1) & 1);
    }

    // ---- epilogue 1: gelu -> H1[n][m] (stride 68) ----
    #pragma unroll
    for (int j = 0; j < 8; j++) {
        int n = ng * 8 + j;
        float bb = b1[n];
        float4 o0, o1;
        o0.x = gelu_f(acc[0][j] + bb); o0.y = gelu_f(acc[1][j] + bb);
        o0.z = gelu_f(acc[2][j] + bb); o0.w = gelu_f(acc[3][j] + bb);
        o1.x = gelu_f(acc[4][j] + bb); o1.y = gelu_f(acc[5][j] + bb);
        o1.z = gelu_f(acc[6][j] + bb); o1.w = gelu_f(acc[7][j] + bb);
        *(float4*)&H1[n * 68 + mg * 8]     = o0;
        *(float4*)&H1[n * 68 + mg * 8 + 4] = o1;
    }
    __syncthreads();

    // ---- GEMM2: [64,256] @ [256,128] ----
    float4 st2[2];
    auto ldg2 = [&](int kt) {
        #pragma unroll
        for (int i = 0; i < 2; i++) {
            int f = t + i * 256;
            int r = f >> 5, c4 = f & 31;
            st2[i] = *(const float4*)(W2 + (size_t)(kt * 16 + r) * 128 + c4 * 4);
        }
    };
    auto sts2 = [&](int buf) {
        #pragma unroll
        for (int i = 0; i < 2; i++) {
            int f = t + i * 256;
            int r = f >> 5, c4 = f & 31;
            *(float4*)&Bs[buf * 2048 + r * 128 + c4 * 4] = st2[i];
        }
    };

    float acc2[8][4];
    #pragma unroll
    for (int i = 0; i < 8; i++)
        #pragma unroll
        for (int j = 0; j < 4; j++) acc2[i][j] = 0.0f;

    ldg2(0); sts2(0);
    for (int kt = 0; kt < 16; kt++) {
        __syncthreads();
        if (kt < 15) ldg2(kt + 1);
        const float* bp = Bs + (kt & 1) * 2048;
        #pragma unroll
        for (int k = 0; k < 16; k++) {
            const float* ar = H1 + (kt * 16 + k) * 68 + mg * 8;
            float4 a0 = *(const float4*)ar;
            float4 a1 = *(const float4*)(ar + 4);
            float4 b0 = *(const float4*)(bp + k * 128 + ng * 4);
            float a[8] = {a0.x, a0.y, a0.z, a0.w, a1.x, a1.y, a1.z, a1.w};
            float bv[4] = {b0.x, b0.y, b0.z, b0.w};
            #pragma unroll
            for (int i = 0; i < 8; i++)
                #pragma unroll
                for (int j = 0; j < 4; j++)
                    acc2[i][j] = fmaf(a[i], bv[j], acc2[i][j]);
        }
        if (kt < 15) sts2((kt + 1) & 1);
    }

    // ---- scatter-add ----
    float bb[4];
    #pragma unroll
    for (int j = 0; j < 4; j++) bb[j] = b2[ng * 4 + j];
    #pragma unroll
    for (int i = 0; i < 8; i++) {
        int ge = e0 + mg * 8 + i;
        int node = dstp[ge];
        float* base = aggr + (size_t)node * 128 + ng * 4;
        atomicAdd(base + 0, acc2[i][0] + bb[0]);
        atomicAdd(base + 1, acc2[i][1] + bb[1]);
        atomicAdd(base + 2, acc2[i][2] + bb[2]);
        atomicAdd(base + 3, acc2[i][3] + bb[3]);
    }
}

// ---------------------------------------------------------------------------
// Attention: one block per (graph, head); 512 threads, one query each.
// K,V resident in SMEM (128KB). Online softmax.
// ---------------------------------------------------------------------------
__global__ __launch_bounds__(512) void attn_kernel(
    const float* __restrict__ qkv, float* __restrict__ o)
{
    extern __shared__ float sm[];
    float* Ks = sm;                 // [512][32]
    float* Vs = sm + 512 * 32;      // [512][32]
    const int t = threadIdx.x;
    const int g = blockIdx.x >> 2;
    const int h = blockIdx.x & 3;
    const size_t gbase = (size_t)g * 512 * 384 + h * 32;

    #pragma unroll
    for (int it = 0; it < 8; it++) {
        int cc = t + it * 512;       // 0..4095
        int j = cc >> 3, c4 = cc & 7;
        const float* row = qkv + gbase + (size_t)j * 384;
        *(float4*)&Ks[j * 32 + c4 * 4] = *(const float4*)(row + 128 + c4 * 4);
        *(float4*)&Vs[j * 32 + c4 * 4] = *(const float4*)(row + 256 + c4 * 4);
    }

    const float scale = 0.17677669529663687f;  // 1/sqrt(32)
    float q[32];
    {
        const float* qp = qkv + gbase + (size_t)t * 384;
        #pragma unroll
        for (int d4 = 0; d4 < 8; d4++) {
            float4 v = *(const float4*)(qp + d4 * 4);
            q[d4 * 4 + 0] = v.x * scale;
            q[d4 * 4 + 1] = v.y * scale;
            q[d4 * 4 + 2] = v.z * scale;
            q[d4 * 4 + 3] = v.w * scale;
        }
    }
    __syncthreads();

    float m = -1e30f, l = 0.0f;
    float oacc[32];
    #pragma unroll
    for (int d = 0; d < 32; d++) oacc[d] = 0.0f;

    for (int j = 0; j < 512; j++) {
        const float* kr = Ks + j * 32;
        float s = 0.0f;
        #pragma unroll
        for (int d4 = 0; d4 < 8; d4++) {
            float4 kv = *(const float4*)(kr + d4 * 4);
            s = fmaf(q[d4 * 4 + 0], kv.x, s);
            s = fmaf(q[d4 * 4 + 1], kv.y, s);
            s = fmaf(q[d4 * 4 + 2], kv.z, s);
            s = fmaf(q[d4 * 4 + 3], kv.w, s);
        }
        if (s > m) {
            float cor = __expf(m - s);
            l *= cor;
            #pragma unroll
            for (int d = 0; d < 32; d++) oacc[d] *= cor;
            m = s;
        }
        float p = __expf(s - m);
        l += p;
        const float* vr = Vs + j * 32;
        #pragma unroll
        for (int d4 = 0; d4 < 8; d4++) {
            float4 vv = *(const float4*)(vr + d4 * 4);
            oacc[d4 * 4 + 0] = fmaf(p, vv.x, oacc[d4 * 4 + 0]);
            oacc[d4 * 4 + 1] = fmaf(p, vv.y, oacc[d4 * 4 + 1]);
            oacc[d4 * 4 + 2] = fmaf(p, vv.z, oacc[d4 * 4 + 2]);
            oacc[d4 * 4 + 3] = fmaf(p, vv.w, oacc[d4 * 4 + 3]);
        }
    }

    float inv = 1.0f / l;
    float* op = o + (size_t)(g * 512 + t) * 128 + h * 32;
    #pragma unroll
    for (int d4 = 0; d4 < 8; d4++) {
        float4 w;
        w.x = oacc[d4 * 4 + 0] * inv;
        w.y = oacc[d4 * 4 + 1] * inv;
        w.z = oacc[d4 * 4 + 2] * inv;
        w.w = oacc[d4 * 4 + 3] * inv;
        *(float4*)(op + d4 * 4) = w;
    }
}

// ---------------------------------------------------------------------------
// Host launcher
// ---------------------------------------------------------------------------
extern "C" void kernel_launch(void* const* d_in, const int* in_sizes, int n_in,
                              void* d_out, int out_size)
{
    const float* x      = (const float*)d_in[0];
    const int*   eidx   = (const int*)  d_in[1];
    const float* ea     = (const float*)d_in[2];
    /* d_in[3] = batch (unused: equal-size graphs) */
    const float* gnn_g  = (const float*)d_in[4];
    const float* gnn_b  = (const float*)d_in[5];
    const float* msg_w1 = (const float*)d_in[6];
    const float* msg_b1 = (const float*)d_in[7];
    const float* msg_w2 = (const float*)d_in[8];
    const float* msg_b2 = (const float*)d_in[9];
    const float* upd_w1 = (const float*)d_in[10];
    const float* upd_b1 = (const float*)d_in[11];
    const float* upd_w2 = (const float*)d_in[12];
    const float* upd_b2 = (const float*)d_in[13];
    const float* in_w   = (const float*)d_in[14];
    const float* in_b   = (const float*)d_in[15];
    const float* out_w  = (const float*)d_in[16];
    const float* out_b  = (const float*)d_in[17];
    const float* ffn_w1 = (const float*)d_in[18];
    const float* ffn_b1 = (const float*)d_in[19];
    const float* ffn_w2 = (const float*)d_in[20];
    const float* ffn_b2 = (const float*)d_in[21];
    const float* n1_g   = (const float*)d_in[22];
    const float* n1_b   = (const float*)d_in[23];
    const float* n2_g   = (const float*)d_in[24];
    const float* n2_b   = (const float*)d_in[25];
    float* out = (float*)d_out;

    float *xn, *aggr, *t1, *hloc, *qkv, *obuf, *hattn, *h1, *ffn, *ffu;
    cudaGetSymbolAddress((void**)&xn,    g_xn);
    cudaGetSymbolAddress((void**)&aggr,  g_aggr);
    cudaGetSymbolAddress((void**)&t1,    g_t1);
    cudaGetSymbolAddress((void**)&hloc,  g_hloc);
    cudaGetSymbolAddress((void**)&qkv,   g_qkv);
    cudaGetSymbolAddress((void**)&obuf,  g_obuf);
    cudaGetSymbolAddress((void**)&hattn, g_hattn);
    cudaGetSymbolAddress((void**)&h1,    g_h1);
    cudaGetSymbolAddress((void**)&ffn,   g_ffn);
    cudaGetSymbolAddress((void**)&ffu,   g_ffu);

    cudaFuncSetAttribute(edge_kernel, cudaFuncAttributeMaxDynamicSharedMemorySize, 176128);
    cudaFuncSetAttribute(attn_kernel, cudaFuncAttributeMaxDynamicSharedMemorySize, 131072);

    // 1) xn = LN(x)
    ln_kernel<<<NV / 8, 256>>>(x, nullptr, nullptr, gnn_g, gnn_b, xn);
    // 2) aggr = 0
    cudaMemsetAsync(aggr, 0, (size_t)NV * DV * sizeof(float), 0);
    // 3) fused edge MLP + scatter-add
    edge_kernel<<<EV / 64, 256, 176128>>>(xn, eidx, ea, msg_w1, msg_b1, msg_w2, msg_b2, aggr);
    // 4) update MLP
    dim3 gu(NV / 128, 128 / 64);
    gemm_bias_kernel<true ><<<gu, 256>>>(xn, 128, aggr, 128, upd_w1, upd_b1, t1,   NV, 128);
    gemm_bias_kernel<false><<<gu, 256>>>(t1, 128, nullptr, 0, upd_w2, upd_b2, hloc, NV, 128);
    // 5) qkv projection
    dim3 gq(NV / 128, 384 / 64);
    gemm_bias_kernel<false><<<gq, 256>>>(x, 128, nullptr, 0, in_w, in_b, qkv, NV, 384);
    // 6) attention
    attn_kernel<<<GV * HV, 512, 131072>>>(qkv, obuf);
    // 7) output projection
    gemm_bias_kernel<false><<<gu, 256>>>(obuf, 128, nullptr, 0, out_w, out_b, hattn, NV, 128);
    // 8) h = LN(x + hloc + hattn)
    ln_kernel<<<NV / 8, 256>>>(x, hloc, hattn, n1_g, n1_b, h1);
    // 9) FFN
    dim3 gf(NV / 128, 256 / 64);
    gemm_bias_kernel<true ><<<gf, 256>>>(h1, 128, nullptr, 0, ffn_w1, ffn_b1, ffn, NV, 256);
    gemm_bias_kernel<false><<<gu, 256>>>(ffn, 256, nullptr, 0, ffn_w2, ffn_b2, ffu, NV, 128);
    // 10) out = LN(h + ffn_out)
    ln_kernel<<<NV / 8, 256>>>(h1, ffu, nullptr, n2_g, n2_b, out);
}

// round 2
// speedup vs baseline: 2.5976x; 2.5976x over previous
#include <cuda_runtime.h>
#include <math.h>

// ---------------------------------------------------------------------------
// Problem constants
// ---------------------------------------------------------------------------
#define NV   16384      // nodes
#define DV   128        // node dim
#define EDV  32         // edge feat dim
#define EV   262144     // edges
#define GV   32         // graphs
#define SV   512        // seq per graph
#define HV   4          // heads
#define HDV  32         // head dim

// ---------------------------------------------------------------------------
// Scratch buffers (device globals; no runtime allocation allowed)
// ---------------------------------------------------------------------------
__device__ float g_xn   [NV * DV];
__device__ float g_pd   [NV * 256];
__device__ float g_ps   [NV * 256];
__device__ float g_pe   [(size_t)EV * 256];
__device__ float g_aggrH[NV * 256];
__device__ float g_aggr [NV * DV];
__device__ float g_t1   [NV * DV];
__device__ float g_hloc [NV * DV];
__device__ float g_qkv  [NV * 3 * DV];
__device__ float g_obuf [NV * DV];
__device__ float g_hattn[NV * DV];
__device__ float g_h1   [NV * DV];
__device__ float g_ffn  [NV * 2 * DV];
__device__ float g_ffu  [NV * DV];
__device__ int   g_cnt   [NV];
__device__ int   g_offs  [NV + 1];
__device__ int   g_cursor[NV];
__device__ int   g_eperm [EV];
__device__ float g_deg   [NV];

// ---------------------------------------------------------------------------
// f32x2 packed-math helpers (FFMA2: 2x fma-pipe throughput, PTX-only)
// ---------------------------------------------------------------------------
typedef unsigned long long u64;

__device__ __forceinline__ u64 pack2(float x, float y) {
    u64 r; asm("mov.b64 %0, {%1, %2};" : "=l"(r) : "f"(x), "f"(y)); return r;
}
__device__ __forceinline__ u64 dup2(float x) {
    u64 r; asm("mov.b64 %0, {%1, %1};" : "=l"(r) : "f"(x)); return r;
}
__device__ __forceinline__ float2 unpack2(u64 v) {
    float2 r; asm("mov.b64 {%0, %1}, %2;" : "=f"(r.x), "=f"(r.y) : "l"(v)); return r;
}
__device__ __forceinline__ void fma2(u64& d, u64 a, u64 b) {
    asm("fma.rn.f32x2 %0, %1, %2, %0;" : "+l"(d) : "l"(a), "l"(b));
}
__device__ __forceinline__ u64 add2(u64 a, u64 b) {
    u64 r; asm("add.rn.f32x2 %0, %1, %2;" : "=l"(r) : "l"(a), "l"(b)); return r;
}
__device__ __forceinline__ u64 mul2(u64 a, u64 b) {
    u64 r; asm("mul.rn.f32x2 %0, %1, %2;" : "=l"(r) : "l"(a), "l"(b)); return r;
}

__device__ __forceinline__ float gelu_f(float v) {
    return 0.5f * v * (1.0f + erff(v * 0.70710678118654752f));
}

// ---------------------------------------------------------------------------
// LayerNorm over D=128 with up to 3 summed inputs. One warp per row.
// ---------------------------------------------------------------------------
__global__ __launch_bounds__(256) void ln_kernel(
    const float* __restrict__ a, const float* __restrict__ b,
    const float* __restrict__ c, const float* __restrict__ g,
    const float* __restrict__ be, float* __restrict__ out)
{
    int row  = blockIdx.x * 8 + (threadIdx.x >> 5);
    int lane = threadIdx.x & 31;
    size_t off = (size_t)row * 128 + lane * 4;
    float4 v = *(const float4*)(a + off);
    if (b) {
        float4 u = *(const float4*)(b + off);
        v.x += u.x; v.y += u.y; v.z += u.z; v.w += u.w;
    }
    if (c) {
        float4 u = *(const float4*)(c + off);
        v.x += u.x; v.y += u.y; v.z += u.z; v.w += u.w;
    }
    float s  = v.x + v.y + v.z + v.w;
    float ss = v.x*v.x + v.y*v.y + v.z*v.z + v.w*v.w;
    #pragma unroll
    for (int o = 16; o > 0; o >>= 1) {
        s  += __shfl_xor_sync(0xffffffffu, s,  o);
        ss += __shfl_xor_sync(0xffffffffu, ss, o);
    }
    float mean = s * (1.0f / 128.0f);
    float var  = ss * (1.0f / 128.0f) - mean * mean;
    float rstd = rsqrtf(var + 1e-5f);
    float4 gg = *(const float4*)(g  + lane * 4);
    float4 bb = *(const float4*)(be + lane * 4);
    float4 o4;
    o4.x = (v.x - mean) * rstd * gg.x + bb.x;
    o4.y = (v.y - mean) * rstd * gg.y + bb.y;
    o4.z = (v.z - mean) * rstd * gg.z + bb.z;
    o4.w = (v.w - mean) * rstd * gg.w + bb.w;
    *(float4*)(out + off) = o4;
}

// ---------------------------------------------------------------------------
// Generic fp32 GEMM with packed FFMA2 inner loop.
// C[M,NN] = act( [A1|A2][M,K1+K2] @ B[K,NN] + rowscale[m]*bias[n] )
// BM=128, BN=64, BK=16, 256 threads; acc packed along M (pairs).
// ---------------------------------------------------------------------------
template<bool GELU>
__global__ __launch_bounds__(256) void gemm_kernel(
    const float* __restrict__ A1, int K1,
    const float* __restrict__ A2, int K2,
    const float* __restrict__ B,
    const float* __restrict__ bias,
    const float* __restrict__ rowscale,
    float* __restrict__ C, int M, int NN)
{
    const int K = K1 + K2;
    const int T = K >> 4;
    __shared__ float As[2][16 * 128];
    __shared__ float Bs[2][16 * 64];
    const int t  = threadIdx.x;
    const int m0 = blockIdx.x * 128;
    const int n0 = blockIdx.y * 64;
    const int mg = t >> 4;       // 0..15  -> rows mg*8 .. mg*8+7
    const int ng = t & 15;       // 0..15  -> cols ng*4 .. ng*4+3

    float4 ra[2], rb;
    auto ldg_tile = [&](int kt) {
        int kb = kt * 16;
        #pragma unroll
        for (int i = 0; i < 2; i++) {
            int cc = t + i * 256;
            int m = cc >> 2, k4 = cc & 3;
            int gk = kb + k4 * 4;
            const float* src = (gk < K1)
                ? (A1 + (size_t)(m0 + m) * K1 + gk)
                : (A2 + (size_t)(m0 + m) * K2 + (gk - K1));
            ra[i] = *(const float4*)src;
        }
        int r = t >> 4, c4 = t & 15;
        rb = *(const float4*)(B + (size_t)(kb + r) * NN + n0 + c4 * 4);
    };
    auto sts_tile = [&](int buf) {
        #pragma unroll
        for (int i = 0; i < 2; i++) {
            int cc = t + i * 256;
            int m = cc >> 2, k4 = cc & 3;
            As[buf][(k4 * 4 + 0) * 128 + m] = ra[i].x;
            As[buf][(k4 * 4 + 1) * 128 + m] = ra[i].y;
            As[buf][(k4 * 4 + 2) * 128 + m] = ra[i].z;
            As[buf][(k4 * 4 + 3) * 128 + m] = ra[i].w;
        }
        int r = t >> 4, c4 = t & 15;
        *(float4*)&Bs[buf][r * 64 + c4 * 4] = rb;
    };

    u64 acc[4][4];   // [m-pair 0..3 -> rows 2i,2i+1][n 0..3]
    #pragma unroll
    for (int i = 0; i < 4; i++)
        #pragma unroll
        for (int j = 0; j < 4; j++) acc[i][j] = 0ull;

    ldg_tile(0); sts_tile(0);
    for (int kt = 0; kt < T; kt++) {
        __syncthreads();
        if (kt + 1 < T) ldg_tile(kt + 1);
        const float* ap = As[kt & 1];
        const float* bp = Bs[kt & 1];
        #pragma unroll
        for (int k = 0; k < 16; k++) {
            ulonglong2 a01 = *(const ulonglong2*)(ap + k * 128 + mg * 8);
            ulonglong2 a23 = *(const ulonglong2*)(ap + k * 128 + mg * 8 + 4);
            float4 b = *(const float4*)(bp + k * 64 + ng * 4);
            u64 am[4] = {a01.x, a01.y, a23.x, a23.y};
            u64 bd[4] = {dup2(b.x), dup2(b.y), dup2(b.z), dup2(b.w)};
            #pragma unroll
            for (int i = 0; i < 4; i++)
                #pragma unroll
                for (int j = 0; j < 4; j++)
                    fma2(acc[i][j], am[i], bd[j]);
        }
        if (kt + 1 < T) sts_tile((kt + 1) & 1);
    }

    float4 bv = bias ? *(const float4*)(bias + n0 + ng * 4)
                     : make_float4(0.f, 0.f, 0.f, 0.f);
    #pragma unroll
    for (int i = 0; i < 4; i++) {
        int r0 = m0 + mg * 8 + 2 * i;
        float rs0 = rowscale ? rowscale[r0]     : 1.0f;
        float rs1 = rowscale ? rowscale[r0 + 1] : 1.0f;
        float2 v0 = unpack2(acc[i][0]);
        float2 v1 = unpack2(acc[i][1]);
        float2 v2 = unpack2(acc[i][2]);
        float2 v3 = unpack2(acc[i][3]);
        float4 lo, hi;
        lo.x = v0.x + rs0 * bv.x; lo.y = v1.x + rs0 * bv.y;
        lo.z = v2.x + rs0 * bv.z; lo.w = v3.x + rs0 * bv.w;
        hi.x = v0.y + rs1 * bv.x; hi.y = v1.y + rs1 * bv.y;
        hi.z = v2.y + rs1 * bv.z; hi.w = v3.y + rs1 * bv.w;
        if (GELU) {
            lo.x = gelu_f(lo.x); lo.y = gelu_f(lo.y);
            lo.z = gelu_f(lo.z); lo.w = gelu_f(lo.w);
            hi.x = gelu_f(hi.x); hi.y = gelu_f(hi.y);
            hi.z = gelu_f(hi.z); hi.w = gelu_f(hi.w);
        }
        *(float4*)(C + (size_t)r0       * NN + n0 + ng * 4) = lo;
        *(float4*)(C + (size_t)(r0 + 1) * NN + n0 + ng * 4) = hi;
    }
}

// ---------------------------------------------------------------------------
// Counting sort of edges by dst: histogram -> scan -> scatter
// ---------------------------------------------------------------------------
__global__ __launch_bounds__(256) void hist_kernel(
    const int* __restrict__ dstp, int* __restrict__ cnt)
{
    int e = blockIdx.x * 256 + threadIdx.x;
    atomicAdd(&cnt[dstp[e]], 1);
}

__global__ __launch_bounds__(1024) void scan_kernel(
    const int* __restrict__ cnt, int* __restrict__ offs,
    float* __restrict__ degf)
{
    __shared__ int wsum[32];
    int t = threadIdx.x;
    int local[16];
    int s = 0;
    #pragma unroll
    for (int i = 0; i < 16; i++) { local[i] = cnt[t * 16 + i]; s += local[i]; }
    int lane = t & 31, wid = t >> 5;
    int v = s;
    #pragma unroll
    for (int o = 1; o < 32; o <<= 1) {
        int u = __shfl_up_sync(0xffffffffu, v, o);
        if (lane >= o) v += u;
    }
    if (lane == 31) wsum[wid] = v;
    __syncthreads();
    if (wid == 0) {
        int w = wsum[lane];
        #pragma unroll
        for (int o = 1; o < 32; o <<= 1) {
            int u = __shfl_up_sync(0xffffffffu, w, o);
            if (lane >= o) w += u;
        }
        wsum[lane] = w;
    }
    __syncthreads();
    int base = (wid ? wsum[wid - 1] : 0) + (v - s);
    #pragma unroll
    for (int i = 0; i < 16; i++) {
        offs[t * 16 + i] = base;
        degf[t * 16 + i] = (float)local[i];
        base += local[i];
    }
    if (t == 1023) offs[NV] = base;
}

__global__ __launch_bounds__(256) void scatter_kernel(
    const int* __restrict__ dstp, int* __restrict__ cursor,
    int* __restrict__ eperm)
{
    int e = blockIdx.x * 256 + threadIdx.x;
    int pos = atomicAdd(&cursor[dstp[e]], 1);
    eperm[pos] = e;
}

// ---------------------------------------------------------------------------
// Segmented aggregation: aggrH[n] = sum_{e: dst=n} gelu(Pd[n]+Ps[src_e]+Pe[e])
// One warp per node; conflict-free, no atomics.
// ---------------------------------------------------------------------------
__global__ __launch_bounds__(256) void aggregate_kernel(
    const float* __restrict__ Pd, const float* __restrict__ Ps,
    const float* __restrict__ Pe, const int* __restrict__ eperm,
    const int* __restrict__ offs, const int* __restrict__ srcp,
    float* __restrict__ aggrH)
{
    int n    = (blockIdx.x * 256 + threadIdx.x) >> 5;
    int lane = threadIdx.x & 31;
    int beg = offs[n], end = offs[n + 1];
    const float* pdr = Pd + (size_t)n * 256;
    float4 pd0 = *(const float4*)(pdr + lane * 4);
    float4 pd1 = *(const float4*)(pdr + 128 + lane * 4);
    float4 a0 = make_float4(0.f, 0.f, 0.f, 0.f);
    float4 a1 = make_float4(0.f, 0.f, 0.f, 0.f);
    for (int j = beg; j < end; j++) {
        int e = eperm[j];
        int s = srcp[e];
        const float* psr = Ps + (size_t)s * 256;
        const float* per = Pe + (size_t)e * 256;
        float4 ps0 = *(const float4*)(psr + lane * 4);
        float4 pe0 = *(const float4*)(per + lane * 4);
        float4 ps1 = *(const float4*)(psr + 128 + lane * 4);
        float4 pe1 = *(const float4*)(per + 128 + lane * 4);
        a0.x += gelu_f(pd0.x + ps0.x + pe0.x);
        a0.y += gelu_f(pd0.y + ps0.y + pe0.y);
        a0.z += gelu_f(pd0.z + ps0.z + pe0.z);
        a0.w += gelu_f(pd0.w + ps0.w + pe0.w);
        a1.x += gelu_f(pd1.x + ps1.x + pe1.x);
        a1.y += gelu_f(pd1.y + ps1.y + pe1.y);
        a1.z += gelu_f(pd1.z + ps1.z + pe1.z);
        a1.w += gelu_f(pd1.w + ps1.w + pe1.w);
    }
    float* outp = aggrH + (size_t)n * 256;
    *(float4*)(outp + lane * 4)       = a0;
    *(float4*)(outp + 128 + lane * 4) = a1;
}

// ---------------------------------------------------------------------------
// Attention: one block per (graph, head); 256 threads, 2 queries each.
// K,V resident in SMEM (128KB). Online softmax, packed f32x2 math.
// ---------------------------------------------------------------------------
__global__ __launch_bounds__(256) void attn_kernel(
    const float* __restrict__ qkv, float* __restrict__ o)
{
    extern __shared__ float sm[];
    float* Ks = sm;                 // [512][32]
    float* Vs = sm + 512 * 32;      // [512][32]
    const int t = threadIdx.x;
    const int g = blockIdx.x >> 2;
    const int h = blockIdx.x & 3;
    const size_t gbase = (size_t)g * 512 * 384 + h * 32;

    #pragma unroll
    for (int it = 0; it < 16; it++) {
        int cc = t + it * 256;       // 0..4095
        int j = cc >> 3, c4 = cc & 7;
        const float* row = qkv + gbase + (size_t)j * 384;
        *(float4*)&Ks[j * 32 + c4 * 4] = *(const float4*)(row + 128 + c4 * 4);
        *(float4*)&Vs[j * 32 + c4 * 4] = *(const float4*)(row + 256 + c4 * 4);
    }

    const float scale = 0.17677669529663687f;  // 1/sqrt(32)
    u64 qp[2][16];
    #pragma unroll
    for (int qi = 0; qi < 2; qi++) {
        const float* qr = qkv + gbase + (size_t)(t + qi * 256) * 384;
        #pragma unroll
        for (int c = 0; c < 8; c++) {
            float4 v = *(const float4*)(qr + c * 4);
            qp[qi][2 * c]     = pack2(v.x * scale, v.y * scale);
            qp[qi][2 * c + 1] = pack2(v.z * scale, v.w * scale);
        }
    }
    __syncthreads();

    float m0 = -1e30f, m1 = -1e30f, l0 = 0.f, l1 = 0.f;
    u64 op0[16], op1[16];
    #pragma unroll
    for (int c = 0; c < 16; c++) { op0[c] = 0ull; op1[c] = 0ull; }

    for (int j = 0; j < 512; j++) {
        const ulonglong2* kr = (const ulonglong2*)(Ks + j * 32);
        u64 sa0 = 0, sb0 = 0, sa1 = 0, sb1 = 0;
        #pragma unroll
        for (int c = 0; c < 8; c++) {
            ulonglong2 kk = kr[c];
            fma2(sa0, qp[0][2 * c],     kk.x);
            fma2(sb0, qp[0][2 * c + 1], kk.y);
            fma2(sa1, qp[1][2 * c],     kk.x);
            fma2(sb1, qp[1][2 * c + 1], kk.y);
        }
        float2 t0 = unpack2(add2(sa0, sb0));
        float2 t1 = unpack2(add2(sa1, sb1));
        float s0 = t0.x + t0.y, s1 = t1.x + t1.y;
        if (s0 > m0) {
            float cr = __expf(m0 - s0); l0 *= cr;
            u64 cd = dup2(cr);
            #pragma unroll
            for (int c = 0; c < 16; c++) op0[c] = mul2(op0[c], cd);
            m0 = s0;
        }
        if (s1 > m1) {
            float cr = __expf(m1 - s1); l1 *= cr;
            u64 cd = dup2(cr);
            #pragma unroll
            for (int c = 0; c < 16; c++) op1[c] = mul2(op1[c], cd);
            m1 = s1;
        }
        float p0 = __expf(s0 - m0), p1 = __expf(s1 - m1);
        l0 += p0; l1 += p1;
        u64 pd0 = dup2(p0), pd1 = dup2(p1);
        const ulonglong2* vr = (const ulonglong2*)(Vs + j * 32);
        #pragma unroll
        for (int c = 0; c < 8; c++) {
            ulonglong2 vv = vr[c];
            fma2(op0[2 * c],     pd0, vv.x);
            fma2(op0[2 * c + 1], pd0, vv.y);
            fma2(op1[2 * c],     pd1, vv.x);
            fma2(op1[2 * c + 1], pd1, vv.y);
        }
    }

    float i0 = 1.0f / l0, i1 = 1.0f / l1;
    {
        float* orow = o + (size_t)(g * 512 + t) * 128 + h * 32;
        #pragma unroll
        for (int c = 0; c < 8; c++) {
            float2 x0 = unpack2(op0[2 * c]);
            float2 x1 = unpack2(op0[2 * c + 1]);
            float4 w = make_float4(x0.x * i0, x0.y * i0, x1.x * i0, x1.y * i0);
            *(float4*)(orow + c * 4) = w;
        }
    }
    {
        float* orow = o + (size_t)(g * 512 + t + 256) * 128 + h * 32;
        #pragma unroll
        for (int c = 0; c < 8; c++) {
            float2 x0 = unpack2(op1[2 * c]);
            float2 x1 = unpack2(op1[2 * c + 1]);
            float4 w = make_float4(x0.x * i1, x0.y * i1, x1.x * i1, x1.y * i1);
            *(float4*)(orow + c * 4) = w;
        }
    }
}

// ---------------------------------------------------------------------------
// Host launcher
// ---------------------------------------------------------------------------
extern "C" void kernel_launch(void* const* d_in, const int* in_sizes, int n_in,
                              void* d_out, int out_size)
{
    const float* x      = (const float*)d_in[0];
    const int*   eidx   = (const int*)  d_in[1];
    const float* ea     = (const float*)d_in[2];
    /* d_in[3] = batch (unused: equal-size graphs) */
    const float* gnn_g  = (const float*)d_in[4];
    const float* gnn_b  = (const float*)d_in[5];
    const float* msg_w1 = (const float*)d_in[6];
    const float* msg_b1 = (const float*)d_in[7];
    const float* msg_w2 = (const float*)d_in[8];
    const float* msg_b2 = (const float*)d_in[9];
    const float* upd_w1 = (const float*)d_in[10];
    const float* upd_b1 = (const float*)d_in[11];
    const float* upd_w2 = (const float*)d_in[12];
    const float* upd_b2 = (const float*)d_in[13];
    const float* in_w   = (const float*)d_in[14];
    const float* in_b   = (const float*)d_in[15];
    const float* out_w  = (const float*)d_in[16];
    const float* out_b  = (const float*)d_in[17];
    const float* ffn_w1 = (const float*)d_in[18];
    const float* ffn_b1 = (const float*)d_in[19];
    const float* ffn_w2 = (const float*)d_in[20];
    const float* ffn_b2 = (const float*)d_in[21];
    const float* n1_g   = (const float*)d_in[22];
    const float* n1_b   = (const float*)d_in[23];
    const float* n2_g   = (const float*)d_in[24];
    const float* n2_b   = (const float*)d_in[25];
    float* out = (float*)d_out;

    const int* srcp = eidx;         // edge_index[0] = source (x_j)
    const int* dstp = eidx + EV;    // edge_index[1] = target (x_i)

    float *xn, *pd, *ps, *pe, *aggrH, *aggr, *t1, *hloc, *qkvb, *obuf, *hattn,
          *h1, *ffn, *ffu, *deg;
    int *cnt, *offs, *cursor, *eperm;
    cudaGetSymbolAddress((void**)&xn,    g_xn);
    cudaGetSymbolAddress((void**)&pd,    g_pd);
    cudaGetSymbolAddress((void**)&ps,    g_ps);
    cudaGetSymbolAddress((void**)&pe,    g_pe);
    cudaGetSymbolAddress((void**)&aggrH, g_aggrH);
    cudaGetSymbolAddress((void**)&aggr,  g_aggr);
    cudaGetSymbolAddress((void**)&t1,    g_t1);
    cudaGetSymbolAddress((void**)&hloc,  g_hloc);
    cudaGetSymbolAddress((void**)&qkvb,  g_qkv);
    cudaGetSymbolAddress((void**)&obuf,  g_obuf);
    cudaGetSymbolAddress((void**)&hattn, g_hattn);
    cudaGetSymbolAddress((void**)&h1,    g_h1);
    cudaGetSymbolAddress((void**)&ffn,   g_ffn);
    cudaGetSymbolAddress((void**)&ffu,   g_ffu);
    cudaGetSymbolAddress((void**)&deg,   g_deg);
    cudaGetSymbolAddress((void**)&cnt,   g_cnt);
    cudaGetSymbolAddress((void**)&offs,  g_offs);
    cudaGetSymbolAddress((void**)&cursor,g_cursor);
    cudaGetSymbolAddress((void**)&eperm, g_eperm);

    cudaFuncSetAttribute(attn_kernel, cudaFuncAttributeMaxDynamicSharedMemorySize, 131072);

    // 1) xn = LN(x)
    ln_kernel<<<NV / 8, 256>>>(x, nullptr, nullptr, gnn_g, gnn_b, xn);

    // 2) projected node tables + edge-feature projection (b1 folded into Pe)
    gemm_kernel<false><<<dim3(NV / 128, 4), 256>>>(
        xn, 128, nullptr, 0, msg_w1,             nullptr, nullptr, pd, NV, 256);
    gemm_kernel<false><<<dim3(NV / 128, 4), 256>>>(
        xn, 128, nullptr, 0, msg_w1 + 128 * 256, nullptr, nullptr, ps, NV, 256);
    gemm_kernel<false><<<dim3(EV / 128, 4), 256>>>(
        ea, 32,  nullptr, 0, msg_w1 + 256 * 256, msg_b1,  nullptr, pe, EV, 256);

    // 3) counting sort of edges by dst
    cudaMemsetAsync(cnt, 0, NV * sizeof(int), 0);
    hist_kernel<<<EV / 256, 256>>>(dstp, cnt);
    scan_kernel<<<1, 1024>>>(cnt, offs, deg);
    cudaMemcpyAsync(cursor, offs, NV * sizeof(int), cudaMemcpyDeviceToDevice, 0);
    scatter_kernel<<<EV / 256, 256>>>(dstp, cursor, eperm);

    // 4) segmented gelu-sum:  aggrH[n] = sum gelu(Pd[n]+Ps[src]+Pe[e])
    aggregate_kernel<<<NV / 8, 256>>>(pd, ps, pe, eperm, offs, srcp, aggrH);

    // 5) aggr = aggrH @ W2 + deg[m]*b2[n]
    gemm_kernel<false><<<dim3(NV / 128, 2), 256>>>(
        aggrH, 256, nullptr, 0, msg_w2, msg_b2, deg, aggr, NV, 128);

    // 6) update MLP
    gemm_kernel<true ><<<dim3(NV / 128, 2), 256>>>(
        xn, 128, aggr, 128, upd_w1, upd_b1, nullptr, t1, NV, 128);
    gemm_kernel<false><<<dim3(NV / 128, 2), 256>>>(
        t1, 128, nullptr, 0, upd_w2, upd_b2, nullptr, hloc, NV, 128);

    // 7) qkv projection + attention + output projection
    gemm_kernel<false><<<dim3(NV / 128, 6), 256>>>(
        x, 128, nullptr, 0, in_w, in_b, nullptr, qkvb, NV, 384);
    attn_kernel<<<GV * HV, 256, 131072>>>(qkvb, obuf);
    gemm_kernel<false><<<dim3(NV / 128, 2), 256>>>(
        obuf, 128, nullptr, 0, out_w, out_b, nullptr, hattn, NV, 128);

    // 8) h = LN(x + hloc + hattn)
    ln_kernel<<<NV / 8, 256>>>(x, hloc, hattn, n1_g, n1_b, h1);

    // 9) FFN
    gemm_kernel<true ><<<dim3(NV / 128, 4), 256>>>(
        h1, 128, nullptr, 0, ffn_w1, ffn_b1, nullptr, ffn, NV, 256);
    gemm_kernel<false><<<dim3(NV / 128, 2), 256>>>(
        ffn, 256, nullptr, 0, ffn_w2, ffn_b2, nullptr, ffu, NV, 128);

    // 10) out = LN(h + ffn_out)
    ln_kernel<<<NV / 8, 256>>>(h1, ffu, nullptr, n2_g, n2_b, out);
}